// round 14
// baseline (speedup 1.0000x reference)
#include <cuda_runtime.h>
#include <cuda_fp16.h>
#include <cstdint>

#define BB 16
#define SS 7500
#define HHID 64
#define NH 4
#define DK 64
#define TT 300
#define JJ 25
#define ROWS (BB*SS)                       // 120000
#define PROJ_ELEMS (BB*JJ*NH*TT*DK)        // 30,720,000

// Scratch (__device__ globals; alloc-free rule). Layout: [b][j][h][t][d]
__device__ __half g_Qp[PROJ_ELEMS];   // fp16 (Wq pre-scaled by log2(e)/8)
__device__ __half g_Kp[PROJ_ELEMS];   // fp16
__device__ __half g_Vp[PROJ_ELEMS];   // fp16 V' = v @ (Wv_h @ Wo_h)
__device__ __half g_Op[PROJ_ELEMS];   // fp16 per-head FINAL contributions
// Pre-transposed fp16 weights (B-operand layout W^T[n][k], packed u32 pairs)
__device__ uint32_t g_Wt[3 * 256 * 32];   // [mat][n 256][w 32] (k = 2w, 2w+1)

// ===========================================================================
// HMMA m16n8k16 f16->f32, f16x2 pack, ldmatrix
// ===========================================================================
__device__ __forceinline__ void mma16816(float* c,
    uint32_t a0, uint32_t a1, uint32_t a2, uint32_t a3,
    uint32_t b0, uint32_t b1)
{
    asm volatile(
        "mma.sync.aligned.m16n8k16.row.col.f32.f16.f16.f32 "
        "{%0,%1,%2,%3}, {%4,%5,%6,%7}, {%8,%9}, {%0,%1,%2,%3};"
        : "+f"(c[0]), "+f"(c[1]), "+f"(c[2]), "+f"(c[3])
        : "r"(a0), "r"(a1), "r"(a2), "r"(a3), "r"(b0), "r"(b1));
}
__device__ __forceinline__ uint32_t pack_f16x2(float a, float b)   // lo=a, hi=b
{
    uint32_t r;
    asm("cvt.rn.f16x2.f32 %0, %2, %1;" : "=r"(r) : "f"(a), "f"(b));
    return r;
}
__device__ __forceinline__ void ldsm4(uint32_t& r0, uint32_t& r1,
                                      uint32_t& r2, uint32_t& r3, uint32_t a)
{
    asm volatile("ldmatrix.sync.aligned.m8n8.x4.shared.b16 {%0,%1,%2,%3}, [%4];"
                 : "=r"(r0), "=r"(r1), "=r"(r2), "=r"(r3) : "r"(a));
}
__device__ __forceinline__ void ldsm2(uint32_t& r0, uint32_t& r1, uint32_t a)
{
    asm volatile("ldmatrix.sync.aligned.m8n8.x2.shared.b16 {%0,%1}, [%2];"
                 : "=r"(r0), "=r"(r1) : "r"(a));
}
// pack two fp32 (log2-domain scores) -> clamped -> 2^x as f16x2
__device__ __forceinline__ uint32_t exp2_pack(float a, float b, __half2 cap)
{
    uint32_t u = pack_f16x2(a, b);
    __half2 h = h2exp2(__hmin2(*(__half2*)&u, cap));
    return *(uint32_t*)&h;
}

// ===========================================================================
// Kernel 0a: pack Wq (scaled by log2e/8) and Wk into B-operand layout.
// ===========================================================================
__global__ __launch_bounds__(256) void prep_qk_kernel(
    const float* __restrict__ Wq, const float* __restrict__ Wk)
{
    int i = blockIdx.x * 256 + threadIdx.x;
    if (i >= 2 * 8192) return;
    int mat = i >> 13, rem = i & 8191;
    int n = rem >> 5, w = rem & 31;
    const float* W = (mat == 0) ? Wq : Wk;
    float sc = (mat == 0) ? 0.125f * 1.4426950408889634f : 1.0f;
    float f0 = W[(2 * w)     * 256 + n] * sc;
    float f1 = W[(2 * w + 1) * 256 + n] * sc;
    g_Wt[i] = pack_f16x2(f0, f1);
}

// ===========================================================================
// Kernel 0b: fold Wo into Wv.  Wv'_h = Wv[:,h*64:+64] @ Wo[h*64:+64,:]
// ===========================================================================
__global__ __launch_bounds__(256) void prep_v_kernel(
    const float* __restrict__ Wv, const float* __restrict__ Wo)
{
    __shared__ float Wvs[64 * 65];
    __shared__ float Wos[64 * 65];

    const int h   = blockIdx.x;
    const int tid = threadIdx.x;

    for (int i = tid; i < 64 * 64; i += 256) {
        int r = i >> 6, c = i & 63;
        Wvs[r * 65 + c] = Wv[r * 256 + h * 64 + c];
        Wos[r * 65 + c] = Wo[(h * 64 + r) * 64 + c];
    }
    __syncthreads();

    const int n  = tid >> 2;
    const int w0 = (tid & 3) * 8;
    #pragma unroll
    for (int ww = 0; ww < 8; ++ww) {
        int w = w0 + ww;
        int k0 = 2 * w, k1 = 2 * w + 1;
        float f0 = 0.f, f1 = 0.f;
        #pragma unroll 8
        for (int m = 0; m < 64; ++m) {
            float wo = Wos[m * 65 + n];
            f0 = fmaf(Wvs[k0 * 65 + m], wo, f0);
            f1 = fmaf(Wvs[k1 * 65 + m], wo, f1);
        }
        g_Wt[2 * 8192 + (h * 64 + n) * 32 + w] = pack_f16x2(f0, f1);
    }
}

// ===========================================================================
// Kernel 1: QKV projection via HMMA.  grid (938, 1, 3), 256 thr.
// ===========================================================================
__global__ __launch_bounds__(256) void qkv_proj_kernel(
    const float* __restrict__ q, const float* __restrict__ k,
    const float* __restrict__ v)
{
    __shared__ uint32_t Xs[128 * 36];
    __shared__ uint32_t Ws[64 * 36];

    const int mat = blockIdx.z;
    const float* x = (mat == 0) ? q : (mat == 1) ? k : v;
    __half* dst    = (mat == 0) ? g_Qp : (mat == 1) ? g_Kp : g_Vp;

    const int row0 = blockIdx.x * 128;
    const int tid  = threadIdx.x;

    for (int i = tid; i < 128 * 16; i += 256) {
        int r = i >> 4, c4 = i & 15;
        int row = row0 + r;
        float4 f = (row < ROWS) ? *(const float4*)&x[(size_t)row * HHID + c4 * 4]
                                : make_float4(0.f, 0.f, 0.f, 0.f);
        Xs[r * 36 + c4 * 2]     = pack_f16x2(f.x, f.y);
        Xs[r * 36 + c4 * 2 + 1] = pack_f16x2(f.z, f.w);
    }
    __syncthreads();

    const int wid  = tid >> 5;
    const int lane = tid & 31;
    const int g    = lane >> 2;
    const int tq   = lane & 3;

    uint32_t qa[4][4];
    {
        const uint32_t* xa = &Xs[(wid * 16 + g) * 36 + tq];
        const uint32_t* xb = &Xs[(wid * 16 + 8 + g) * 36 + tq];
        #pragma unroll
        for (int kc = 0; kc < 4; ++kc) {
            qa[kc][0] = xa[kc * 8];
            qa[kc][1] = xb[kc * 8];
            qa[kc][2] = xa[kc * 8 + 4];
            qa[kc][3] = xb[kc * 8 + 4];
        }
    }

    const int rA = row0 + wid * 16 + g;
    const int rB = rA + 8;
    size_t oA = 0, oB = 0;
    if (rA < ROWS) {
        int b_ = rA / SS, s = rA % SS, jg = s / TT, t = s % TT;
        oA = ((((size_t)b_ * JJ + jg) * NH) * TT + t) * DK + 2 * tq;
    }
    if (rB < ROWS) {
        int b_ = rB / SS, s = rB % SS, jg = s / TT, t = s % TT;
        oB = ((((size_t)b_ * JJ + jg) * NH) * TT + t) * DK + 2 * tq;
    }

    for (int h = 0; h < NH; ++h) {
        __syncthreads();
        for (int i = tid; i < 64 * 32; i += 256) {
            int n = i >> 5, w = i & 31;
            Ws[n * 36 + w] = g_Wt[mat * 8192 + (h * 64 + n) * 32 + w];
        }
        __syncthreads();

        float c[8][4];
        #pragma unroll
        for (int nt = 0; nt < 8; ++nt)
            #pragma unroll
            for (int j = 0; j < 4; ++j) c[nt][j] = 0.f;

        #pragma unroll
        for (int nt = 0; nt < 8; ++nt) {
            const uint32_t* wb = &Ws[(nt * 8 + g) * 36 + tq];
            #pragma unroll
            for (int kc = 0; kc < 4; ++kc)
                mma16816(c[nt], qa[kc][0], qa[kc][1], qa[kc][2], qa[kc][3],
                         wb[kc * 8], wb[kc * 8 + 4]);
        }

        const size_t hoff = (size_t)h * (TT * DK);
        if (rA < ROWS) {
            __half* p = dst + oA + hoff;
            #pragma unroll
            for (int nt = 0; nt < 8; ++nt)
                *(uint32_t*)(p + nt * 8) = pack_f16x2(c[nt][0], c[nt][1]);
        }
        if (rB < ROWS) {
            __half* p = dst + oB + hoff;
            #pragma unroll
            for (int nt = 0; nt < 8; ++nt)
                *(uint32_t*)(p + nt * 8) = pack_f16x2(c[nt][2], c[nt][3]);
        }
    }
}

// ===========================================================================
// Kernel 2: HMMA attention.  grid = 3200: CTA = (b,j,h, half).
//   half 0 -> M-tiles 0..9 (rows 0..159), half 1 -> tiles 10..18.
//   Critical path per CTA: 2 tiles/warp (was 3).  K/V staged per CTA.
// ===========================================================================
#define KPITCH_W 36
#define VPITCH_W 156
#define VROWS    72
#define SM_K_BYTES  (304 * KPITCH_W * 4)
#define SM_V_BYTES  (VROWS * VPITCH_W * 4)
#define ATT_SMEM    (SM_K_BYTES + SM_V_BYTES)

__global__ __launch_bounds__(256, 2) void attn_hmma_kernel()
{
    extern __shared__ uint32_t smw[];
    uint32_t* Ksw = smw;
    uint32_t* Vtw = smw + 304 * KPITCH_W;
    __half*   Vth = (__half*)Vtw;

    const int tid  = threadIdx.x;
    const int wid  = tid >> 5;
    const int lane = tid & 31;
    const int g    = lane >> 2;
    const int tq   = lane & 3;

    const int bjh  = blockIdx.x >> 1;
    const int half = blockIdx.x & 1;
    const size_t base = (size_t)bjh * (TT * DK);
    const uint32_t* kg = (const uint32_t*)(g_Kp + base);
    const uint32_t* vg = (const uint32_t*)(g_Vp + base);
    const uint32_t* qg = (const uint32_t*)(g_Qp + base);

    for (int i = tid; i < TT * 32; i += 256) {
        int t = i >> 5, p = i & 31;
        Ksw[t * KPITCH_W + p] = kg[i];
    }
    for (int i = tid; i < 4 * 32; i += 256) {
        int t = TT + (i >> 5), p = i & 31;
        Ksw[t * KPITCH_W + p] = 0u;
    }
    for (int i = tid; i < TT * 32; i += 256) {
        int t = i >> 5, p = i & 31;
        uint32_t w = vg[i];
        int d0 = 2 * p;
        Vth[d0 * 312 + t]       = __ushort_as_half((unsigned short)(w & 0xffff));
        Vth[(d0 + 1) * 312 + t] = __ushort_as_half((unsigned short)(w >> 16));
    }
    for (int i = tid; i < 64 * 4; i += 256) {       // V pad t=300..303
        int d = i >> 2, t = TT + (i & 3);
        Vth[d * 312 + t] = __ushort_as_half(0);
    }
    // ones-tile rows 64..71 (row 64 = 1.0 for t<TT, else 0)
    for (int i = tid; i < 8 * VPITCH_W; i += 256) {
        int r = 64 + i / VPITCH_W, w = i % VPITCH_W;
        uint32_t val = 0u;
        if (r == 64) {
            int t0 = 2 * w;
            uint32_t lo = (t0     < TT) ? 0x3C00u : 0u;
            uint32_t hi = (t0 + 1 < TT) ? 0x3C00u : 0u;
            val = lo | (hi << 16);
        }
        Vtw[r * VPITCH_W + w] = val;
    }
    __syncthreads();

    // ldmatrix per-lane addressing
    const int lrow  = (lane & 7) + ((lane >> 4) << 3);   // 0..15
    const int lcolh = ((lane >> 3) & 1) * 8;             // 0 or 8 halves
    const uint32_t ksh = (uint32_t)__cvta_generic_to_shared(Ksw)
                       + (uint32_t)(lrow * (KPITCH_W * 4) + lcolh * 2);
    const uint32_t vsh = (uint32_t)__cvta_generic_to_shared(Vtw)
                       + (uint32_t)(lrow * (VPITCH_W * 4) + lcolh * 2);
    const uint32_t vsh1 = (uint32_t)__cvta_generic_to_shared(Vtw)
                        + (uint32_t)((64 + (lane & 7)) * (VPITCH_W * 4) + lcolh * 2);

    const __half2 cap = __floats2half2_rn(15.5f, 15.5f);

    const int mEnd = (half == 0) ? 10 : 19;
    for (int m = half * 10 + wid; m < mEnd; m += 8) {
        const int rA = m * 16 + g;
        const int rB = rA + 8;

        uint32_t qa[4][4];
        #pragma unroll
        for (int kc = 0; kc < 4; ++kc) {
            int wlo = kc * 8 + tq;
            qa[kc][0] = (rA < TT) ? qg[rA * 32 + wlo]     : 0u;
            qa[kc][1] = (rB < TT) ? qg[rB * 32 + wlo]     : 0u;
            qa[kc][2] = (rA < TT) ? qg[rA * 32 + wlo + 4] : 0u;
            qa[kc][3] = (rB < TT) ? qg[rB * 32 + wlo + 4] : 0u;
        }

        float o[8][4];
        #pragma unroll
        for (int nt = 0; nt < 8; ++nt)
            #pragma unroll
            for (int j = 0; j < 4; ++j) o[nt][j] = 0.f;
        float osum[4] = {0.f, 0.f, 0.f, 0.f};

        #pragma unroll 2
        for (int kv = 0; kv < 19; ++kv) {
            float c0[4] = {0.f, 0.f, 0.f, 0.f};
            float c1[4] = {0.f, 0.f, 0.f, 0.f};
            {
                uint32_t ka = ksh + (uint32_t)(kv * 16 * (KPITCH_W * 4));
                #pragma unroll
                for (int kc = 0; kc < 4; ++kc) {
                    uint32_t b0, b1, b2, b3;
                    ldsm4(b0, b1, b2, b3, ka + kc * 32);
                    mma16816(c0, qa[kc][0], qa[kc][1], qa[kc][2], qa[kc][3], b0, b1);
                    mma16816(c1, qa[kc][0], qa[kc][1], qa[kc][2], qa[kc][3], b2, b3);
                }
            }

            // softmax in log2 domain: P = 2^min(s,15.5), fp16x2 MUFU
            uint32_t pa0 = exp2_pack(c0[0], c0[1], cap);
            uint32_t pa1 = exp2_pack(c0[2], c0[3], cap);
            uint32_t pa2 = exp2_pack(c1[0], c1[1], cap);
            uint32_t pa3 = exp2_pack(c1[2], c1[3], cap);

            {
                uint32_t va = vsh + (uint32_t)(kv * 32);
                #pragma unroll
                for (int j = 0; j < 4; ++j) {
                    uint32_t r0, r1, r2, r3;
                    ldsm4(r0, r1, r2, r3, va + (uint32_t)(j * 16 * (VPITCH_W * 4)));
                    mma16816(o[2 * j],     pa0, pa1, pa2, pa3, r0, r1);
                    mma16816(o[2 * j + 1], pa0, pa1, pa2, pa3, r2, r3);
                }
                // row-sum via ones-tile
                uint32_t s0, s1;
                ldsm2(s0, s1, vsh1 + (uint32_t)(kv * 32));
                mma16816(osum, pa0, pa1, pa2, pa3, s0, s1);
            }
        }

        // broadcast sums (col 64 lives in tq=0 lanes: osum[0]=rA, osum[2]=rB)
        const float sAf = __shfl_sync(0xffffffffu, osum[0], lane & 28);
        const float sBf = __shfl_sync(0xffffffffu, osum[2], lane & 28);
        const float rA_inv = 1.0f / sAf;
        const float rB_inv = 1.0f / sBf;

        if (rA < TT) {
            __half* op = g_Op + base + (size_t)rA * DK + 2 * tq;
            #pragma unroll
            for (int nt = 0; nt < 8; ++nt)
                *(uint32_t*)(op + nt * 8) =
                    pack_f16x2(o[nt][0] * rA_inv, o[nt][1] * rA_inv);
        }
        if (rB < TT) {
            __half* op = g_Op + base + (size_t)rB * DK + 2 * tq;
            #pragma unroll
            for (int nt = 0; nt < 8; ++nt)
                *(uint32_t*)(op + nt * 8) =
                    pack_f16x2(o[nt][2] * rB_inv, o[nt][3] * rB_inv);
        }
    }
}

// ===========================================================================
// Kernel 3: head reduce.  out[row, d] = sum_h g_Op[b,j,h,t,d]
// ===========================================================================
__global__ __launch_bounds__(256) void head_reduce_kernel(float* __restrict__ out)
{
    const int i = blockIdx.x * 256 + threadIdx.x;
    if (i >= ROWS * 16) return;
    const int row = i >> 4;
    const int c4  = i & 15;
    const int b_  = row / SS, s = row % SS;
    const int jg  = s / TT, t = s % TT;

    const size_t hb = (((size_t)b_ * JJ + jg) * NH) * (TT * DK) + t * DK + c4 * 4;
    float acc0 = 0.f, acc1 = 0.f, acc2 = 0.f, acc3 = 0.f;
    #pragma unroll
    for (int h = 0; h < NH; ++h) {
        const __half* p = g_Op + hb + (size_t)h * (TT * DK);
        uint2 w = *(const uint2*)p;
        __half2 h01 = *(__half2*)&w.x;
        __half2 h23 = *(__half2*)&w.y;
        float2 f01 = __half22float2(h01);
        float2 f23 = __half22float2(h23);
        acc0 += f01.x; acc1 += f01.y; acc2 += f23.x; acc3 += f23.y;
    }
    *(float4*)&out[(size_t)row * HHID + c4 * 4] =
        make_float4(acc0, acc1, acc2, acc3);
}

// ---------------------------------------------------------------------------
extern "C" void kernel_launch(void* const* d_in, const int* in_sizes, int n_in,
                              void* d_out, int out_size)
{
    (void)in_sizes; (void)n_in; (void)out_size;
    const float* q  = (const float*)d_in[0];
    const float* k  = (const float*)d_in[1];
    const float* v  = (const float*)d_in[2];
    const float* Wq = (const float*)d_in[3];
    const float* Wk = (const float*)d_in[4];
    const float* Wv = (const float*)d_in[5];
    const float* Wo = (const float*)d_in[6];
    float* out = (float*)d_out;

    cudaFuncSetAttribute(attn_hmma_kernel,
                         cudaFuncAttributeMaxDynamicSharedMemorySize, ATT_SMEM);

    prep_qk_kernel<<<64, 256>>>(Wq, Wk);
    prep_v_kernel<<<NH, 256>>>(Wv, Wo);

    const int MB = (ROWS + 127) / 128;   // 938
    dim3 g1(MB, 1, 3);
    qkv_proj_kernel<<<g1, 256>>>(q, k, v);

    attn_hmma_kernel<<<BB * JJ * NH * 2, 256, ATT_SMEM>>>();

    head_reduce_kernel<<<(ROWS * 16 + 255) / 256, 256>>>(out);
}

// round 15
// speedup vs baseline: 1.2674x; 1.2674x over previous
#include <cuda_runtime.h>
#include <cuda_fp16.h>
#include <cstdint>

#define BB 16
#define SS 7500
#define HHID 64
#define NH 4
#define DK 64
#define TT 300
#define JJ 25
#define ROWS (BB*SS)                       // 120000
#define PROJ_ELEMS (BB*JJ*NH*TT*DK)        // 30,720,000

// Scratch (__device__ globals; alloc-free rule). Layout: [b][j][h][t][d]
__device__ __half g_Qp[PROJ_ELEMS];   // fp16 (Wq pre-scaled by log2(e)/8)
__device__ __half g_Kp[PROJ_ELEMS];   // fp16
__device__ __half g_Vp[PROJ_ELEMS];   // fp16 V' = v @ (Wv_h @ Wo_h)
__device__ __half g_Op[PROJ_ELEMS];   // fp16 per-head FINAL contributions
// Pre-transposed fp16 weights (B-operand layout W^T[n][k], packed u32 pairs)
__device__ uint32_t g_Wt[3 * 256 * 32];   // [mat][n 256][w 32] (k = 2w, 2w+1)

// ===========================================================================
// HMMA m16n8k16 f16->f32, f16x2 pack, ldmatrix (normal + trans)
// ===========================================================================
__device__ __forceinline__ void mma16816(float* c,
    uint32_t a0, uint32_t a1, uint32_t a2, uint32_t a3,
    uint32_t b0, uint32_t b1)
{
    asm volatile(
        "mma.sync.aligned.m16n8k16.row.col.f32.f16.f16.f32 "
        "{%0,%1,%2,%3}, {%4,%5,%6,%7}, {%8,%9}, {%0,%1,%2,%3};"
        : "+f"(c[0]), "+f"(c[1]), "+f"(c[2]), "+f"(c[3])
        : "r"(a0), "r"(a1), "r"(a2), "r"(a3), "r"(b0), "r"(b1));
}
__device__ __forceinline__ uint32_t pack_f16x2(float a, float b)   // lo=a, hi=b
{
    uint32_t r;
    asm("cvt.rn.f16x2.f32 %0, %2, %1;" : "=r"(r) : "f"(a), "f"(b));
    return r;
}
__device__ __forceinline__ void ldsm4(uint32_t& r0, uint32_t& r1,
                                      uint32_t& r2, uint32_t& r3, uint32_t a)
{
    asm volatile("ldmatrix.sync.aligned.m8n8.x4.shared.b16 {%0,%1,%2,%3}, [%4];"
                 : "=r"(r0), "=r"(r1), "=r"(r2), "=r"(r3) : "r"(a));
}
__device__ __forceinline__ void ldsm4t(uint32_t& r0, uint32_t& r1,
                                       uint32_t& r2, uint32_t& r3, uint32_t a)
{
    asm volatile("ldmatrix.sync.aligned.m8n8.x4.trans.shared.b16 {%0,%1,%2,%3}, [%4];"
                 : "=r"(r0), "=r"(r1), "=r"(r2), "=r"(r3) : "r"(a));
}
__device__ __forceinline__ void ldsm2t(uint32_t& r0, uint32_t& r1, uint32_t a)
{
    asm volatile("ldmatrix.sync.aligned.m8n8.x2.trans.shared.b16 {%0,%1}, [%2];"
                 : "=r"(r0), "=r"(r1) : "r"(a));
}
// pack two fp32 (log2-domain scores) -> clamped -> 2^x as f16x2
__device__ __forceinline__ uint32_t exp2_pack(float a, float b, __half2 cap)
{
    uint32_t u = pack_f16x2(a, b);
    __half2 h = h2exp2(__hmin2(*(__half2*)&u, cap));
    return *(uint32_t*)&h;
}

// ===========================================================================
// Kernel 0a: pack Wq (scaled by log2e/8) and Wk into B-operand layout.
// ===========================================================================
__global__ __launch_bounds__(256) void prep_qk_kernel(
    const float* __restrict__ Wq, const float* __restrict__ Wk)
{
    int i = blockIdx.x * 256 + threadIdx.x;
    if (i >= 2 * 8192) return;
    int mat = i >> 13, rem = i & 8191;
    int n = rem >> 5, w = rem & 31;
    const float* W = (mat == 0) ? Wq : Wk;
    float sc = (mat == 0) ? 0.125f * 1.4426950408889634f : 1.0f;
    float f0 = W[(2 * w)     * 256 + n] * sc;
    float f1 = W[(2 * w + 1) * 256 + n] * sc;
    g_Wt[i] = pack_f16x2(f0, f1);
}

// ===========================================================================
// Kernel 0b: fold Wo into Wv.  Wv'_h = Wv[:,h*64:+64] @ Wo[h*64:+64,:]
// ===========================================================================
__global__ __launch_bounds__(256) void prep_v_kernel(
    const float* __restrict__ Wv, const float* __restrict__ Wo)
{
    __shared__ float Wvs[64 * 65];
    __shared__ float Wos[64 * 65];

    const int h   = blockIdx.x;
    const int tid = threadIdx.x;

    for (int i = tid; i < 64 * 64; i += 256) {
        int r = i >> 6, c = i & 63;
        Wvs[r * 65 + c] = Wv[r * 256 + h * 64 + c];
        Wos[r * 65 + c] = Wo[(h * 64 + r) * 64 + c];
    }
    __syncthreads();

    const int n  = tid >> 2;
    const int w0 = (tid & 3) * 8;
    #pragma unroll
    for (int ww = 0; ww < 8; ++ww) {
        int w = w0 + ww;
        int k0 = 2 * w, k1 = 2 * w + 1;
        float f0 = 0.f, f1 = 0.f;
        #pragma unroll 8
        for (int m = 0; m < 64; ++m) {
            float wo = Wos[m * 65 + n];
            f0 = fmaf(Wvs[k0 * 65 + m], wo, f0);
            f1 = fmaf(Wvs[k1 * 65 + m], wo, f1);
        }
        g_Wt[2 * 8192 + (h * 64 + n) * 32 + w] = pack_f16x2(f0, f1);
    }
}

// ===========================================================================
// Kernel 1: QKV projection via HMMA.  grid (938, 1, 3), 256 thr.
// ===========================================================================
__global__ __launch_bounds__(256) void qkv_proj_kernel(
    const float* __restrict__ q, const float* __restrict__ k,
    const float* __restrict__ v)
{
    __shared__ uint32_t Xs[128 * 36];
    __shared__ uint32_t Ws[64 * 36];

    const int mat = blockIdx.z;
    const float* x = (mat == 0) ? q : (mat == 1) ? k : v;
    __half* dst    = (mat == 0) ? g_Qp : (mat == 1) ? g_Kp : g_Vp;

    const int row0 = blockIdx.x * 128;
    const int tid  = threadIdx.x;

    for (int i = tid; i < 128 * 16; i += 256) {
        int r = i >> 4, c4 = i & 15;
        int row = row0 + r;
        float4 f = (row < ROWS) ? *(const float4*)&x[(size_t)row * HHID + c4 * 4]
                                : make_float4(0.f, 0.f, 0.f, 0.f);
        Xs[r * 36 + c4 * 2]     = pack_f16x2(f.x, f.y);
        Xs[r * 36 + c4 * 2 + 1] = pack_f16x2(f.z, f.w);
    }
    __syncthreads();

    const int wid  = tid >> 5;
    const int lane = tid & 31;
    const int g    = lane >> 2;
    const int tq   = lane & 3;

    uint32_t qa[4][4];
    {
        const uint32_t* xa = &Xs[(wid * 16 + g) * 36 + tq];
        const uint32_t* xb = &Xs[(wid * 16 + 8 + g) * 36 + tq];
        #pragma unroll
        for (int kc = 0; kc < 4; ++kc) {
            qa[kc][0] = xa[kc * 8];
            qa[kc][1] = xb[kc * 8];
            qa[kc][2] = xa[kc * 8 + 4];
            qa[kc][3] = xb[kc * 8 + 4];
        }
    }

    const int rA = row0 + wid * 16 + g;
    const int rB = rA + 8;
    size_t oA = 0, oB = 0;
    if (rA < ROWS) {
        int b_ = rA / SS, s = rA % SS, jg = s / TT, t = s % TT;
        oA = ((((size_t)b_ * JJ + jg) * NH) * TT + t) * DK + 2 * tq;
    }
    if (rB < ROWS) {
        int b_ = rB / SS, s = rB % SS, jg = s / TT, t = s % TT;
        oB = ((((size_t)b_ * JJ + jg) * NH) * TT + t) * DK + 2 * tq;
    }

    for (int h = 0; h < NH; ++h) {
        __syncthreads();
        for (int i = tid; i < 64 * 32; i += 256) {
            int n = i >> 5, w = i & 31;
            Ws[n * 36 + w] = g_Wt[mat * 8192 + (h * 64 + n) * 32 + w];
        }
        __syncthreads();

        float c[8][4];
        #pragma unroll
        for (int nt = 0; nt < 8; ++nt)
            #pragma unroll
            for (int j = 0; j < 4; ++j) c[nt][j] = 0.f;

        #pragma unroll
        for (int nt = 0; nt < 8; ++nt) {
            const uint32_t* wb = &Ws[(nt * 8 + g) * 36 + tq];
            #pragma unroll
            for (int kc = 0; kc < 4; ++kc)
                mma16816(c[nt], qa[kc][0], qa[kc][1], qa[kc][2], qa[kc][3],
                         wb[kc * 8], wb[kc * 8 + 4]);
        }

        const size_t hoff = (size_t)h * (TT * DK);
        if (rA < ROWS) {
            __half* p = dst + oA + hoff;
            #pragma unroll
            for (int nt = 0; nt < 8; ++nt)
                *(uint32_t*)(p + nt * 8) = pack_f16x2(c[nt][0], c[nt][1]);
        }
        if (rB < ROWS) {
            __half* p = dst + oB + hoff;
            #pragma unroll
            for (int nt = 0; nt < 8; ++nt)
                *(uint32_t*)(p + nt * 8) = pack_f16x2(c[nt][2], c[nt][3]);
        }
    }
}

// ===========================================================================
// Kernel 2: HMMA attention.  grid 1600 (one CTA per (b,j,h)), 8 warps.
//   K smem [304 t][36w] natural layout (normal ldsm).
//   V smem [304 t][36w] natural layout: words 0-31 = V[t][d], word 32 lo =
//   1.0 ones-col (t<300), rest 0.  PV B-operands via ldmatrix.x4.TRANS;
//   ones-column via ldmatrix.x2.trans -> row-sums in osum (9th n8 tile).
// ===========================================================================
#define KPITCH_W 36
#define SM_K_BYTES  (304 * KPITCH_W * 4)    // 43776
#define SM_V_BYTES  (304 * KPITCH_W * 4)    // 43776
#define ATT_SMEM    (SM_K_BYTES + SM_V_BYTES)

__global__ __launch_bounds__(256, 2) void attn_hmma_kernel()
{
    extern __shared__ uint32_t smw[];
    uint32_t* Ksw = smw;
    uint32_t* Vsw = smw + 304 * KPITCH_W;

    const int tid  = threadIdx.x;
    const int wid  = tid >> 5;
    const int lane = tid & 31;
    const int g    = lane >> 2;
    const int tq   = lane & 3;

    const size_t base = (size_t)blockIdx.x * (TT * DK);
    const uint32_t* kg = (const uint32_t*)(g_Kp + base);
    const uint32_t* vg = (const uint32_t*)(g_Vp + base);
    const uint32_t* qg = (const uint32_t*)(g_Qp + base);

    // ---- K: direct u32 copy, rows t, pitch 36w ----
    for (int i = tid; i < TT * 32; i += 256) {
        int t = i >> 5, p = i & 31;
        Ksw[t * KPITCH_W + p] = kg[i];
    }
    for (int i = tid; i < 4 * 32; i += 256) {        // pad t=300..303
        int t = TT + (i >> 5), p = i & 31;
        Ksw[t * KPITCH_W + p] = 0u;
    }
    // ---- V: direct u32 copy (same layout as K) ----
    for (int i = tid; i < TT * 32; i += 256) {
        int t = i >> 5, p = i & 31;
        Vsw[t * KPITCH_W + p] = vg[i];
    }
    for (int i = tid; i < 4 * 32; i += 256) {        // pad t=300..303
        int t = TT + (i >> 5), p = i & 31;
        Vsw[t * KPITCH_W + p] = 0u;
    }
    // ---- ones-column block: words 32..35 of every row (col 64 = 1.0, t<TT) ----
    for (int i = tid; i < 304 * 4; i += 256) {
        int t = i >> 2, p = 32 + (i & 3);
        Vsw[t * KPITCH_W + p] = (p == 32 && t < TT) ? 0x00003C00u : 0u;
    }
    __syncthreads();

    // K (normal ldsm): lane -> row (t-tile row), col half
    const int lrow  = (lane & 7) + ((lane >> 4) << 3);   // 0..15
    const int lcolh = ((lane >> 3) & 1) * 8;             // 0 or 8 halves
    const uint32_t ksh = (uint32_t)__cvta_generic_to_shared(Ksw)
                       + (uint32_t)(lrow * (KPITCH_W * 4) + lcolh * 2);
    // V (trans ldsm x4): lane -> row t0+(lane&15), col block dA + ((lane>>4)*8)
    const uint32_t vbase = (uint32_t)__cvta_generic_to_shared(Vsw);
    const uint32_t vsh4  = vbase + (uint32_t)((lane & 15) * (KPITCH_W * 4)
                                              + ((lane >> 4) << 4));
    // ones (trans ldsm x2): lanes 0..15 -> row t0+lane, col 64 (byte 128)
    const uint32_t vsh1  = vbase + (uint32_t)((lane & 15) * (KPITCH_W * 4) + 128);

    const __half2 cap = __floats2half2_rn(15.5f, 15.5f);

    for (int m = wid; m < 19; m += 8) {
        const int rA = m * 16 + g;
        const int rB = rA + 8;

        uint32_t qa[4][4];
        #pragma unroll
        for (int kc = 0; kc < 4; ++kc) {
            int wlo = kc * 8 + tq;
            qa[kc][0] = (rA < TT) ? qg[rA * 32 + wlo]     : 0u;
            qa[kc][1] = (rB < TT) ? qg[rB * 32 + wlo]     : 0u;
            qa[kc][2] = (rA < TT) ? qg[rA * 32 + wlo + 4] : 0u;
            qa[kc][3] = (rB < TT) ? qg[rB * 32 + wlo + 4] : 0u;
        }

        float o[8][4];
        #pragma unroll
        for (int nt = 0; nt < 8; ++nt)
            #pragma unroll
            for (int j = 0; j < 4; ++j) o[nt][j] = 0.f;
        float osum[4] = {0.f, 0.f, 0.f, 0.f};

        #pragma unroll 2
        for (int kv = 0; kv < 19; ++kv) {
            float c0[4] = {0.f, 0.f, 0.f, 0.f};
            float c1[4] = {0.f, 0.f, 0.f, 0.f};
            {
                uint32_t ka = ksh + (uint32_t)(kv * 16 * (KPITCH_W * 4));
                #pragma unroll
                for (int kc = 0; kc < 4; ++kc) {
                    uint32_t b0, b1, b2, b3;
                    ldsm4(b0, b1, b2, b3, ka + kc * 32);
                    mma16816(c0, qa[kc][0], qa[kc][1], qa[kc][2], qa[kc][3], b0, b1);
                    mma16816(c1, qa[kc][0], qa[kc][1], qa[kc][2], qa[kc][3], b2, b3);
                }
            }

            // softmax in log2 domain: P = 2^min(s,15.5), fp16x2 MUFU
            uint32_t pa0 = exp2_pack(c0[0], c0[1], cap);
            uint32_t pa1 = exp2_pack(c0[2], c0[3], cap);
            uint32_t pa2 = exp2_pack(c1[0], c1[1], cap);
            uint32_t pa3 = exp2_pack(c1[2], c1[3], cap);

            {
                const uint32_t va = vsh4 + (uint32_t)(kv * 16 * (KPITCH_W * 4));
                #pragma unroll
                for (int j = 0; j < 4; ++j) {
                    uint32_t r0, r1, r2, r3;
                    ldsm4t(r0, r1, r2, r3, va + (uint32_t)(j * 32));
                    mma16816(o[2 * j],     pa0, pa1, pa2, pa3, r0, r1);
                    mma16816(o[2 * j + 1], pa0, pa1, pa2, pa3, r2, r3);
                }
                // row-sums via ones-column tile
                uint32_t s0, s1;
                ldsm2t(s0, s1, vsh1 + (uint32_t)(kv * 16 * (KPITCH_W * 4)));
                mma16816(osum, pa0, pa1, pa2, pa3, s0, s1);
            }
        }

        // broadcast sums (col 64 lives in tq=0 lanes: osum[0]=rA, osum[2]=rB)
        const float sAf = __shfl_sync(0xffffffffu, osum[0], lane & 28);
        const float sBf = __shfl_sync(0xffffffffu, osum[2], lane & 28);
        const float rA_inv = 1.0f / sAf;
        const float rB_inv = 1.0f / sBf;

        if (rA < TT) {
            __half* op = g_Op + base + (size_t)rA * DK + 2 * tq;
            #pragma unroll
            for (int nt = 0; nt < 8; ++nt)
                *(uint32_t*)(op + nt * 8) =
                    pack_f16x2(o[nt][0] * rA_inv, o[nt][1] * rA_inv);
        }
        if (rB < TT) {
            __half* op = g_Op + base + (size_t)rB * DK + 2 * tq;
            #pragma unroll
            for (int nt = 0; nt < 8; ++nt)
                *(uint32_t*)(op + nt * 8) =
                    pack_f16x2(o[nt][2] * rB_inv, o[nt][3] * rB_inv);
        }
    }
}

// ===========================================================================
// Kernel 3: head reduce.  out[row, d] = sum_h g_Op[b,j,h,t,d]
// ===========================================================================
__global__ __launch_bounds__(256) void head_reduce_kernel(float* __restrict__ out)
{
    const int i = blockIdx.x * 256 + threadIdx.x;
    if (i >= ROWS * 16) return;
    const int row = i >> 4;
    const int c4  = i & 15;
    const int b_  = row / SS, s = row % SS;
    const int jg  = s / TT, t = s % TT;

    const size_t hb = (((size_t)b_ * JJ + jg) * NH) * (TT * DK) + t * DK + c4 * 4;
    float acc0 = 0.f, acc1 = 0.f, acc2 = 0.f, acc3 = 0.f;
    #pragma unroll
    for (int h = 0; h < NH; ++h) {
        const __half* p = g_Op + hb + (size_t)h * (TT * DK);
        uint2 w = *(const uint2*)p;
        __half2 h01 = *(__half2*)&w.x;
        __half2 h23 = *(__half2*)&w.y;
        float2 f01 = __half22float2(h01);
        float2 f23 = __half22float2(h23);
        acc0 += f01.x; acc1 += f01.y; acc2 += f23.x; acc3 += f23.y;
    }
    *(float4*)&out[(size_t)row * HHID + c4 * 4] =
        make_float4(acc0, acc1, acc2, acc3);
}

// ---------------------------------------------------------------------------
extern "C" void kernel_launch(void* const* d_in, const int* in_sizes, int n_in,
                              void* d_out, int out_size)
{
    (void)in_sizes; (void)n_in; (void)out_size;
    const float* q  = (const float*)d_in[0];
    const float* k  = (const float*)d_in[1];
    const float* v  = (const float*)d_in[2];
    const float* Wq = (const float*)d_in[3];
    const float* Wk = (const float*)d_in[4];
    const float* Wv = (const float*)d_in[5];
    const float* Wo = (const float*)d_in[6];
    float* out = (float*)d_out;

    cudaFuncSetAttribute(attn_hmma_kernel,
                         cudaFuncAttributeMaxDynamicSharedMemorySize, ATT_SMEM);

    prep_qk_kernel<<<64, 256>>>(Wq, Wk);
    prep_v_kernel<<<NH, 256>>>(Wv, Wo);

    const int MB = (ROWS + 127) / 128;   // 938
    dim3 g1(MB, 1, 3);
    qkv_proj_kernel<<<g1, 256>>>(q, k, v);

    attn_hmma_kernel<<<BB * JJ * NH, 256, ATT_SMEM>>>();

    head_reduce_kernel<<<(ROWS * 16 + 255) / 256, 256>>>(out);
}

// round 16
// speedup vs baseline: 1.3116x; 1.0349x over previous
#include <cuda_runtime.h>
#include <cuda_fp16.h>
#include <cstdint>

#define BB 16
#define SS 7500
#define HHID 64
#define NH 4
#define DK 64
#define TT 300
#define JJ 25
#define ROWS (BB*SS)                       // 120000
#define PROJ_ELEMS (BB*JJ*NH*TT*DK)        // 30,720,000

// Scratch (__device__ globals; alloc-free rule). Layout: [b][j][h][t][d]
__device__ __half g_Qp[PROJ_ELEMS];   // fp16 (Wq pre-scaled by log2(e)/8)
__device__ __half g_Kp[PROJ_ELEMS];   // fp16
__device__ __half g_Vp[PROJ_ELEMS];   // fp16 V' = v @ (Wv_h @ Wo_h)
__device__ __half g_Op[PROJ_ELEMS];   // fp16 per-head FINAL contributions
// Pre-transposed fp16 weights (B-operand layout W^T[n][k], packed u32 pairs)
__device__ uint32_t g_Wt[3 * 256 * 32];   // [mat][n 256][w 32] (k = 2w, 2w+1)

// ===========================================================================
// HMMA m16n8k16 f16->f32, f16x2 pack, ldmatrix (normal + trans)
// ===========================================================================
__device__ __forceinline__ void mma16816(float* c,
    uint32_t a0, uint32_t a1, uint32_t a2, uint32_t a3,
    uint32_t b0, uint32_t b1)
{
    asm volatile(
        "mma.sync.aligned.m16n8k16.row.col.f32.f16.f16.f32 "
        "{%0,%1,%2,%3}, {%4,%5,%6,%7}, {%8,%9}, {%0,%1,%2,%3};"
        : "+f"(c[0]), "+f"(c[1]), "+f"(c[2]), "+f"(c[3])
        : "r"(a0), "r"(a1), "r"(a2), "r"(a3), "r"(b0), "r"(b1));
}
__device__ __forceinline__ uint32_t pack_f16x2(float a, float b)   // lo=a, hi=b
{
    uint32_t r;
    asm("cvt.rn.f16x2.f32 %0, %2, %1;" : "=r"(r) : "f"(a), "f"(b));
    return r;
}
__device__ __forceinline__ void ldsm4(uint32_t& r0, uint32_t& r1,
                                      uint32_t& r2, uint32_t& r3, uint32_t a)
{
    asm volatile("ldmatrix.sync.aligned.m8n8.x4.shared.b16 {%0,%1,%2,%3}, [%4];"
                 : "=r"(r0), "=r"(r1), "=r"(r2), "=r"(r3) : "r"(a));
}
__device__ __forceinline__ void ldsm4t(uint32_t& r0, uint32_t& r1,
                                       uint32_t& r2, uint32_t& r3, uint32_t a)
{
    asm volatile("ldmatrix.sync.aligned.m8n8.x4.trans.shared.b16 {%0,%1,%2,%3}, [%4];"
                 : "=r"(r0), "=r"(r1), "=r"(r2), "=r"(r3) : "r"(a));
}
__device__ __forceinline__ void ldsm2t(uint32_t& r0, uint32_t& r1, uint32_t a)
{
    asm volatile("ldmatrix.sync.aligned.m8n8.x2.trans.shared.b16 {%0,%1}, [%2];"
                 : "=r"(r0), "=r"(r1) : "r"(a));
}
// pack two fp32 (log2-domain scores) -> clamped -> 2^x as f16x2
__device__ __forceinline__ uint32_t exp2_pack(float a, float b, __half2 cap)
{
    uint32_t u = pack_f16x2(a, b);
    __half2 h = h2exp2(__hmin2(*(__half2*)&u, cap));
    return *(uint32_t*)&h;
}

// ===========================================================================
// Kernel 0a: pack Wq (scaled by log2e/8) and Wk into B-operand layout.
// ===========================================================================
__global__ __launch_bounds__(256) void prep_qk_kernel(
    const float* __restrict__ Wq, const float* __restrict__ Wk)
{
    int i = blockIdx.x * 256 + threadIdx.x;
    if (i >= 2 * 8192) return;
    int mat = i >> 13, rem = i & 8191;
    int n = rem >> 5, w = rem & 31;
    const float* W = (mat == 0) ? Wq : Wk;
    float sc = (mat == 0) ? 0.125f * 1.4426950408889634f : 1.0f;
    float f0 = W[(2 * w)     * 256 + n] * sc;
    float f1 = W[(2 * w + 1) * 256 + n] * sc;
    g_Wt[i] = pack_f16x2(f0, f1);
}

// ===========================================================================
// Kernel 0b: fold Wo into Wv.  Wv'_h = Wv[:,h*64:+64] @ Wo[h*64:+64,:]
// ===========================================================================
__global__ __launch_bounds__(256) void prep_v_kernel(
    const float* __restrict__ Wv, const float* __restrict__ Wo)
{
    __shared__ float Wvs[64 * 65];
    __shared__ float Wos[64 * 65];

    const int h   = blockIdx.x;
    const int tid = threadIdx.x;

    for (int i = tid; i < 64 * 64; i += 256) {
        int r = i >> 6, c = i & 63;
        Wvs[r * 65 + c] = Wv[r * 256 + h * 64 + c];
        Wos[r * 65 + c] = Wo[(h * 64 + r) * 64 + c];
    }
    __syncthreads();

    const int n  = tid >> 2;
    const int w0 = (tid & 3) * 8;
    #pragma unroll
    for (int ww = 0; ww < 8; ++ww) {
        int w = w0 + ww;
        int k0 = 2 * w, k1 = 2 * w + 1;
        float f0 = 0.f, f1 = 0.f;
        #pragma unroll 8
        for (int m = 0; m < 64; ++m) {
            float wo = Wos[m * 65 + n];
            f0 = fmaf(Wvs[k0 * 65 + m], wo, f0);
            f1 = fmaf(Wvs[k1 * 65 + m], wo, f1);
        }
        g_Wt[2 * 8192 + (h * 64 + n) * 32 + w] = pack_f16x2(f0, f1);
    }
}

// ===========================================================================
// Kernel 1: QKV projection via HMMA.  grid (938, 1, 3), 256 thr.
//   All 4 heads' W staged once.  Output staged in smem, written as
//   coalesced 128B uint4 row-lines.
//   Dynamic smem: Xs[128*36] | Ws[256*36] | Os[128*36]  (72 KB)
// ===========================================================================
#define QKV_SMEM ((128*36 + 256*36 + 128*36) * 4)

__global__ __launch_bounds__(256) void qkv_proj_kernel(
    const float* __restrict__ q, const float* __restrict__ k,
    const float* __restrict__ v)
{
    extern __shared__ uint32_t qsm[];
    uint32_t* Xs = qsm;                 // [128][36w]
    uint32_t* Ws = qsm + 128 * 36;      // [256n][36w]
    uint32_t* Os = qsm + 128 * 36 + 256 * 36;   // [128][36w]

    const int mat = blockIdx.z;
    const float* x = (mat == 0) ? q : (mat == 1) ? k : v;
    __half* dst    = (mat == 0) ? g_Qp : (mat == 1) ? g_Kp : g_Vp;

    const int row0 = blockIdx.x * 128;
    const int tid  = threadIdx.x;

    for (int i = tid; i < 128 * 16; i += 256) {
        int r = i >> 4, c4 = i & 15;
        int row = row0 + r;
        float4 f = (row < ROWS) ? *(const float4*)&x[(size_t)row * HHID + c4 * 4]
                                : make_float4(0.f, 0.f, 0.f, 0.f);
        Xs[r * 36 + c4 * 2]     = pack_f16x2(f.x, f.y);
        Xs[r * 36 + c4 * 2 + 1] = pack_f16x2(f.z, f.w);
    }
    // stage W for ALL 4 heads (n = 0..255)
    for (int i = tid; i < 256 * 32; i += 256) {
        int n = i >> 5, w = i & 31;
        Ws[n * 36 + w] = g_Wt[mat * 8192 + n * 32 + w];
    }
    __syncthreads();

    const int wid  = tid >> 5;
    const int lane = tid & 31;
    const int g    = lane >> 2;
    const int tq   = lane & 3;

    // A fragments (loaded once)
    uint32_t qa[4][4];
    {
        const uint32_t* xa = &Xs[(wid * 16 + g) * 36 + tq];
        const uint32_t* xb = &Xs[(wid * 16 + 8 + g) * 36 + tq];
        #pragma unroll
        for (int kc = 0; kc < 4; ++kc) {
            qa[kc][0] = xa[kc * 8];
            qa[kc][1] = xb[kc * 8];
            qa[kc][2] = xa[kc * 8 + 4];
            qa[kc][3] = xb[kc * 8 + 4];
        }
    }

    // precompute per-thread writeback slots (4 uint4-lines per head)
    int  lds_off[4];
    size_t ob[4];
    bool okj[4];
    #pragma unroll
    for (int j = 0; j < 4; ++j) {
        int i = tid + j * 256;          // 0..1023
        int r = i >> 3, qd = i & 7;     // r: row in tile, qd: uint4 index
        lds_off[j] = r * 36 + qd * 4;
        int row = row0 + r;
        okj[j] = (row < ROWS);
        if (okj[j]) {
            int b_ = row / SS, s = row % SS, jg = s / TT, t = s % TT;
            ob[j] = ((size_t)(b_ * JJ + jg) * NH) * (TT * DK)
                  + (size_t)t * DK + qd * 8;       // halves
        } else ob[j] = 0;
    }

    const int smRowA = wid * 16 + g;
    const int smRowB = smRowA + 8;

    for (int h = 0; h < NH; ++h) {
        float c[8][4];
        #pragma unroll
        for (int nt = 0; nt < 8; ++nt)
            #pragma unroll
            for (int j = 0; j < 4; ++j) c[nt][j] = 0.f;

        #pragma unroll
        for (int nt = 0; nt < 8; ++nt) {
            const uint32_t* wb = &Ws[(h * 64 + nt * 8 + g) * 36 + tq];
            #pragma unroll
            for (int kc = 0; kc < 4; ++kc)
                mma16816(c[nt], qa[kc][0], qa[kc][1], qa[kc][2], qa[kc][3],
                         wb[kc * 8], wb[kc * 8 + 4]);
        }

        // pack into Os (conflict-free: banks 4g + 4nt + tq)
        #pragma unroll
        for (int nt = 0; nt < 8; ++nt) {
            Os[smRowA * 36 + nt * 4 + tq] = pack_f16x2(c[nt][0], c[nt][1]);
            Os[smRowB * 36 + nt * 4 + tq] = pack_f16x2(c[nt][2], c[nt][3]);
        }
        __syncthreads();

        // coalesced writeback: 8 lanes per 128B row line
        const size_t hoff = (size_t)h * (TT * DK);
        #pragma unroll
        for (int j = 0; j < 4; ++j) {
            if (okj[j])
                *(uint4*)(dst + ob[j] + hoff) = *(uint4*)&Os[lds_off[j]];
        }
        __syncthreads();
    }
}

// ===========================================================================
// Kernel 2: HMMA attention.  grid 1600 (one CTA per (b,j,h)), 8 warps.
//   K/V natural [t][36w] layout; V words 32: ones column (row-sum trick).
//   QK accumulators split into 2 chains of 2 to halve MMA dep latency.
// ===========================================================================
#define KPITCH_W 36
#define SM_K_BYTES  (304 * KPITCH_W * 4)    // 43776
#define SM_V_BYTES  (304 * KPITCH_W * 4)    // 43776
#define ATT_SMEM    (SM_K_BYTES + SM_V_BYTES)

__global__ __launch_bounds__(256, 2) void attn_hmma_kernel()
{
    extern __shared__ uint32_t smw[];
    uint32_t* Ksw = smw;
    uint32_t* Vsw = smw + 304 * KPITCH_W;

    const int tid  = threadIdx.x;
    const int wid  = tid >> 5;
    const int lane = tid & 31;
    const int g    = lane >> 2;
    const int tq   = lane & 3;

    const size_t base = (size_t)blockIdx.x * (TT * DK);
    const uint32_t* kg = (const uint32_t*)(g_Kp + base);
    const uint32_t* vg = (const uint32_t*)(g_Vp + base);
    const uint32_t* qg = (const uint32_t*)(g_Qp + base);

    for (int i = tid; i < TT * 32; i += 256) {
        int t = i >> 5, p = i & 31;
        Ksw[t * KPITCH_W + p] = kg[i];
    }
    for (int i = tid; i < 4 * 32; i += 256) {
        int t = TT + (i >> 5), p = i & 31;
        Ksw[t * KPITCH_W + p] = 0u;
    }
    for (int i = tid; i < TT * 32; i += 256) {
        int t = i >> 5, p = i & 31;
        Vsw[t * KPITCH_W + p] = vg[i];
    }
    for (int i = tid; i < 4 * 32; i += 256) {
        int t = TT + (i >> 5), p = i & 31;
        Vsw[t * KPITCH_W + p] = 0u;
    }
    // ones-column block: words 32..35 of every row (col 64 = 1.0, t<TT)
    for (int i = tid; i < 304 * 4; i += 256) {
        int t = i >> 2, p = 32 + (i & 3);
        Vsw[t * KPITCH_W + p] = (p == 32 && t < TT) ? 0x00003C00u : 0u;
    }
    __syncthreads();

    const int lrow  = (lane & 7) + ((lane >> 4) << 3);
    const int lcolh = ((lane >> 3) & 1) * 8;
    const uint32_t ksh = (uint32_t)__cvta_generic_to_shared(Ksw)
                       + (uint32_t)(lrow * (KPITCH_W * 4) + lcolh * 2);
    const uint32_t vbase = (uint32_t)__cvta_generic_to_shared(Vsw);
    const uint32_t vsh4  = vbase + (uint32_t)((lane & 15) * (KPITCH_W * 4)
                                              + ((lane >> 4) << 4));
    const uint32_t vsh1  = vbase + (uint32_t)((lane & 15) * (KPITCH_W * 4) + 128);

    const __half2 cap = __floats2half2_rn(15.5f, 15.5f);

    for (int m = wid; m < 19; m += 8) {
        const int rA = m * 16 + g;
        const int rB = rA + 8;

        uint32_t qa[4][4];
        #pragma unroll
        for (int kc = 0; kc < 4; ++kc) {
            int wlo = kc * 8 + tq;
            qa[kc][0] = (rA < TT) ? qg[rA * 32 + wlo]     : 0u;
            qa[kc][1] = (rB < TT) ? qg[rB * 32 + wlo]     : 0u;
            qa[kc][2] = (rA < TT) ? qg[rA * 32 + wlo + 4] : 0u;
            qa[kc][3] = (rB < TT) ? qg[rB * 32 + wlo + 4] : 0u;
        }

        float o[8][4];
        #pragma unroll
        for (int nt = 0; nt < 8; ++nt)
            #pragma unroll
            for (int j = 0; j < 4; ++j) o[nt][j] = 0.f;
        float osum[4] = {0.f, 0.f, 0.f, 0.f};

        #pragma unroll 2
        for (int kv = 0; kv < 19; ++kv) {
            float c0a[4] = {0.f, 0.f, 0.f, 0.f};
            float c0b[4] = {0.f, 0.f, 0.f, 0.f};
            float c1a[4] = {0.f, 0.f, 0.f, 0.f};
            float c1b[4] = {0.f, 0.f, 0.f, 0.f};
            {
                uint32_t ka = ksh + (uint32_t)(kv * 16 * (KPITCH_W * 4));
                #pragma unroll
                for (int kc = 0; kc < 4; ++kc) {
                    uint32_t b0, b1, b2, b3;
                    ldsm4(b0, b1, b2, b3, ka + kc * 32);
                    float* cc0 = (kc < 2) ? c0a : c0b;
                    float* cc1 = (kc < 2) ? c1a : c1b;
                    mma16816(cc0, qa[kc][0], qa[kc][1], qa[kc][2], qa[kc][3], b0, b1);
                    mma16816(cc1, qa[kc][0], qa[kc][1], qa[kc][2], qa[kc][3], b2, b3);
                }
            }

            // merge split accumulators + softmax in log2 domain
            uint32_t pa0 = exp2_pack(c0a[0] + c0b[0], c0a[1] + c0b[1], cap);
            uint32_t pa1 = exp2_pack(c0a[2] + c0b[2], c0a[3] + c0b[3], cap);
            uint32_t pa2 = exp2_pack(c1a[0] + c1b[0], c1a[1] + c1b[1], cap);
            uint32_t pa3 = exp2_pack(c1a[2] + c1b[2], c1a[3] + c1b[3], cap);

            {
                const uint32_t va = vsh4 + (uint32_t)(kv * 16 * (KPITCH_W * 4));
                #pragma unroll
                for (int j = 0; j < 4; ++j) {
                    uint32_t r0, r1, r2, r3;
                    ldsm4t(r0, r1, r2, r3, va + (uint32_t)(j * 32));
                    mma16816(o[2 * j],     pa0, pa1, pa2, pa3, r0, r1);
                    mma16816(o[2 * j + 1], pa0, pa1, pa2, pa3, r2, r3);
                }
                uint32_t s0, s1;
                ldsm2t(s0, s1, vsh1 + (uint32_t)(kv * 16 * (KPITCH_W * 4)));
                mma16816(osum, pa0, pa1, pa2, pa3, s0, s1);
            }
        }

        const float sAf = __shfl_sync(0xffffffffu, osum[0], lane & 28);
        const float sBf = __shfl_sync(0xffffffffu, osum[2], lane & 28);
        const float rA_inv = 1.0f / sAf;
        const float rB_inv = 1.0f / sBf;

        if (rA < TT) {
            __half* op = g_Op + base + (size_t)rA * DK + 2 * tq;
            #pragma unroll
            for (int nt = 0; nt < 8; ++nt)
                *(uint32_t*)(op + nt * 8) =
                    pack_f16x2(o[nt][0] * rA_inv, o[nt][1] * rA_inv);
        }
        if (rB < TT) {
            __half* op = g_Op + base + (size_t)rB * DK + 2 * tq;
            #pragma unroll
            for (int nt = 0; nt < 8; ++nt)
                *(uint32_t*)(op + nt * 8) =
                    pack_f16x2(o[nt][2] * rB_inv, o[nt][3] * rB_inv);
        }
    }
}

// ===========================================================================
// Kernel 3: head reduce.  out[row, d] = sum_h g_Op[b,j,h,t,d]
// ===========================================================================
__global__ __launch_bounds__(256) void head_reduce_kernel(float* __restrict__ out)
{
    const int i = blockIdx.x * 256 + threadIdx.x;
    if (i >= ROWS * 16) return;
    const int row = i >> 4;
    const int c4  = i & 15;
    const int b_  = row / SS, s = row % SS;
    const int jg  = s / TT, t = s % TT;

    const size_t hb = (((size_t)b_ * JJ + jg) * NH) * (TT * DK) + t * DK + c4 * 4;
    float acc0 = 0.f, acc1 = 0.f, acc2 = 0.f, acc3 = 0.f;
    #pragma unroll
    for (int h = 0; h < NH; ++h) {
        const __half* p = g_Op + hb + (size_t)h * (TT * DK);
        uint2 w = *(const uint2*)p;
        __half2 h01 = *(__half2*)&w.x;
        __half2 h23 = *(__half2*)&w.y;
        float2 f01 = __half22float2(h01);
        float2 f23 = __half22float2(h23);
        acc0 += f01.x; acc1 += f01.y; acc2 += f23.x; acc3 += f23.y;
    }
    *(float4*)&out[(size_t)row * HHID + c4 * 4] =
        make_float4(acc0, acc1, acc2, acc3);
}

// ---------------------------------------------------------------------------
extern "C" void kernel_launch(void* const* d_in, const int* in_sizes, int n_in,
                              void* d_out, int out_size)
{
    (void)in_sizes; (void)n_in; (void)out_size;
    const float* q  = (const float*)d_in[0];
    const float* k  = (const float*)d_in[1];
    const float* v  = (const float*)d_in[2];
    const float* Wq = (const float*)d_in[3];
    const float* Wk = (const float*)d_in[4];
    const float* Wv = (const float*)d_in[5];
    const float* Wo = (const float*)d_in[6];
    float* out = (float*)d_out;

    cudaFuncSetAttribute(attn_hmma_kernel,
                         cudaFuncAttributeMaxDynamicSharedMemorySize, ATT_SMEM);
    cudaFuncSetAttribute(qkv_proj_kernel,
                         cudaFuncAttributeMaxDynamicSharedMemorySize, QKV_SMEM);

    prep_qk_kernel<<<64, 256>>>(Wq, Wk);
    prep_v_kernel<<<NH, 256>>>(Wv, Wo);

    const int MB = (ROWS + 127) / 128;   // 938
    dim3 g1(MB, 1, 3);
    qkv_proj_kernel<<<g1, 256, QKV_SMEM>>>(q, k, v);

    attn_hmma_kernel<<<BB * JJ * NH, 256, ATT_SMEM>>>();

    head_reduce_kernel<<<(ROWS * 16 + 255) / 256, 256>>>(out);
}